// round 9
// baseline (speedup 1.0000x reference)
#include <cuda_runtime.h>
#include <math.h>
#include <stdint.h>

#define N_EMBED 1024
#define SLEN    2048
#define BATCH   4
#define NHEADS  16
#define HDIM    64
#define MROWS   (BATCH * SLEN)        // 8192

// Scratch (device globals: allocation-free rule)
__device__ float g_qkv[(size_t)MROWS * 3 * N_EMBED];  // [8192, 3072] fp32
__device__ float g_y[(size_t)MROWS * N_EMBED];        // [8192, 1024] tf32 bits
__device__ float g_cvt[(size_t)MROWS * N_EMBED        // x_tf32
                     + (size_t)N_EMBED * 3 * N_EMBED  // Wattn_tf32
                     + (size_t)N_EMBED * N_EMBED];    // Wproj_tf32

// ---------------------------------------------------------------------------
// Helpers
// ---------------------------------------------------------------------------
__device__ __forceinline__ uint32_t f2tf32(float f) {
    uint32_t r;
    asm("cvt.rna.tf32.f32 %0, %1;" : "=r"(r) : "f"(f));
    return r;
}
__device__ __forceinline__ void mma_tf32(float d[4], const uint32_t a[4], const uint32_t b[2]) {
    asm volatile(
        "mma.sync.aligned.m16n8k8.row.col.f32.tf32.tf32.f32 "
        "{%0,%1,%2,%3}, {%4,%5,%6,%7}, {%8,%9}, {%0,%1,%2,%3};"
        : "+f"(d[0]), "+f"(d[1]), "+f"(d[2]), "+f"(d[3])
        : "r"(a[0]), "r"(a[1]), "r"(a[2]), "r"(a[3]), "r"(b[0]), "r"(b[1]));
}
__device__ __forceinline__ uint32_t smem_u32(const void* p) {
    uint32_t a;
    asm("{ .reg .u64 t; cvta.to.shared.u64 t, %1; cvt.u32.u64 %0, t; }" : "=r"(a) : "l"(p));
    return a;
}
__device__ __forceinline__ void cp_async16(uint32_t saddr, const void* g) {
    asm volatile("cp.async.cg.shared.global [%0], [%1], 16;" :: "r"(saddr), "l"(g));
}
#define CP_COMMIT()  asm volatile("cp.async.commit_group;" ::: "memory")
#define CP_WAIT(n)   asm volatile("cp.async.wait_group %0;" :: "n"(n) : "memory")

// ---------------------------------------------------------------------------
// Elementwise fp32 -> tf32-bit-pattern conversion (vectorized, grid-stride).
// ---------------------------------------------------------------------------
__global__ __launch_bounds__(256)
void cvt_tf32_kernel(const float* __restrict__ in, float* __restrict__ out, int n) {
    const int stride = gridDim.x * blockDim.x * 4;
    for (int i = (blockIdx.x * blockDim.x + threadIdx.x) * 4; i < n; i += stride) {
        float4 v = *reinterpret_cast<const float4*>(in + i);
        float4 o;
        o.x = __uint_as_float(f2tf32(v.x));
        o.y = __uint_as_float(f2tf32(v.y));
        o.z = __uint_as_float(f2tf32(v.z));
        o.w = __uint_as_float(f2tf32(v.w));
        *reinterpret_cast<float4*>(out + i) = o;
    }
}

// ---------------------------------------------------------------------------
// tf32 mma.sync GEMM v7: C[M,N] = A[M,K] @ B[K,N] + bias[N]
// A, B hold tf32 BIT PATTERNS already (no cvt in kernel).
// BM=BN=128, BK=16; 256 threads = 8 warps (2x4), warp tile 64x32.
// 4-stage cp.async.cg pipeline; 2 CTAs/SM -> 16 warps/SM.
// smem/stage: 128*20 + 16*136 = 4736 words; 4 stages = 75776 bytes.
// ---------------------------------------------------------------------------
#define G_AS 20
#define G_BS 136
#define G_ASTG (128 * G_AS)
#define G_BSTG (16 * G_BS)
#define G_STG_WORDS (G_ASTG + G_BSTG)
#define G_SMEM_BYTES (4 * G_STG_WORDS * 4)

__global__ __launch_bounds__(256, 2)
void mma_gemm_kernel(const float* __restrict__ A, const float* __restrict__ B,
                     const float* __restrict__ bias, float* __restrict__ C,
                     int M, int N, int K) {
    extern __shared__ uint32_t gsm[];

    const int tid   = threadIdx.x;
    const int lane  = tid & 31;
    const int wid   = tid >> 5;           // 0..7
    const int gid   = lane >> 2;
    const int tig   = lane & 3;
    const int warpM = wid >> 2;           // 0..1 -> 64 rows
    const int warpN = wid & 3;            // 0..3 -> 32 cols
    const int row0  = blockIdx.y * 128;
    const int col0  = blockIdx.x * 128;

    const uint32_t uS = smem_u32(gsm);

    // Per-stage load mapping: A 128x16 (512 float4), B 16x128 (512 float4),
    // 256 threads -> 2 chunks each.
    const int arow = tid >> 2, ac = (tid & 3) * 4;   // A rows + i*64
    const int brow = tid >> 5, bc = (tid & 31) * 4;  // B rows + i*8

    auto issue = [&](int kt, int stg) {
        const float* Ag = A + (size_t)row0 * K + kt * 16;
        const float* Bg = B + (size_t)(kt * 16) * N + col0;
        const uint32_t sa = uS + (uint32_t)(stg * G_STG_WORDS) * 4;
        const uint32_t sb = sa + (uint32_t)G_ASTG * 4;
        #pragma unroll
        for (int i = 0; i < 2; i++)
            cp_async16(sa + (uint32_t)((arow + i * 64) * G_AS + ac) * 4,
                       Ag + (size_t)(arow + i * 64) * K + ac);
        #pragma unroll
        for (int i = 0; i < 2; i++)
            cp_async16(sb + (uint32_t)((brow + i * 8) * G_BS + bc) * 4,
                       Bg + (size_t)(brow + i * 8) * N + bc);
        CP_COMMIT();
    };

    float acc[4][4][4];
    #pragma unroll
    for (int i = 0; i < 4; i++)
        #pragma unroll
        for (int j = 0; j < 4; j++)
            #pragma unroll
            for (int r = 0; r < 4; r++) acc[i][j][r] = 0.f;

    const int NT = K / 16;

    issue(0, 0); issue(1, 1); issue(2, 2);

    for (int kt = 0; kt < NT; kt++) {
        if (kt < NT - 2) { CP_WAIT(2); } else { CP_WAIT(0); }
        __syncthreads();

        const uint32_t* As = gsm + (kt & 3) * G_STG_WORDS;
        const uint32_t* Bs = As + G_ASTG;

        #pragma unroll
        for (int ks = 0; ks < 2; ks++) {
            const int kb = ks * 8;
            uint32_t a[4][4], b[4][2];
            #pragma unroll
            for (int mf = 0; mf < 4; mf++) {
                const int r = warpM * 64 + mf * 16;
                a[mf][0] = As[(r + gid)     * G_AS + kb + tig];
                a[mf][1] = As[(r + gid + 8) * G_AS + kb + tig];
                a[mf][2] = As[(r + gid)     * G_AS + kb + tig + 4];
                a[mf][3] = As[(r + gid + 8) * G_AS + kb + tig + 4];
            }
            #pragma unroll
            for (int nf = 0; nf < 4; nf++) {
                const int c = warpN * 32 + nf * 8 + gid;
                b[nf][0] = Bs[(kb + tig)     * G_BS + c];
                b[nf][1] = Bs[(kb + tig + 4) * G_BS + c];
            }
            #pragma unroll
            for (int mf = 0; mf < 4; mf++)
                #pragma unroll
                for (int nf = 0; nf < 4; nf++)
                    mma_tf32(acc[mf][nf], a[mf], b[nf]);
        }
        if (kt + 3 < NT) issue(kt + 3, (kt + 3) & 3);
    }

    // Epilogue: add bias, store fp32
    #pragma unroll
    for (int mf = 0; mf < 4; mf++) {
        const size_t rbase = (size_t)row0 + warpM * 64 + mf * 16 + gid;
        #pragma unroll
        for (int nf = 0; nf < 4; nf++) {
            const int col = col0 + warpN * 32 + nf * 8 + tig * 2;
            const float2 bz = *reinterpret_cast<const float2*>(bias + col);
            float2 v0, v1;
            v0.x = acc[mf][nf][0] + bz.x; v0.y = acc[mf][nf][1] + bz.y;
            v1.x = acc[mf][nf][2] + bz.x; v1.y = acc[mf][nf][3] + bz.y;
            *reinterpret_cast<float2*>(C + rbase * N + col)       = v0;
            *reinterpret_cast<float2*>(C + (rbase + 8) * N + col) = v1;
        }
    }
}

// ---------------------------------------------------------------------------
// Flash attention, tf32 mma.sync, 2-term QK split, K/V register prefetch.
// CTA = 64 q-rows x head x batch; 4 warps (128 thr) x 16 q-rows; 64-key chunks.
// 2 CTAs/SM. Writes y as tf32 bit patterns (consumed directly by proj GEMM).
// SMEM words (stride 76): Kh[64*76] Vs[64*76] Ps[64*76] = 192*76 (58368 B)
// Q staging overlay: Qhi[64*76] Qlo[64*76] over Kh/Vs.
// ---------------------------------------------------------------------------
#define STR 76
#define FA_SMEM_BYTES (192 * STR * 4)

__global__ __launch_bounds__(128, 2)
void flash_attn_mma_kernel(const float* __restrict__ qkv, float* __restrict__ y) {
    extern __shared__ uint32_t sm[];
    uint32_t* Kh  = sm;                      // 64*76
    uint32_t* Vs  = sm + 64 * STR;           // 64*76
    uint32_t* Ps  = sm + 128 * STR;          // 64*76
    uint32_t* Qhi = sm;                      // overlay
    uint32_t* Qlo = sm + 64 * STR;           // overlay

    const int qt  = (gridDim.x - 1) - blockIdx.x;   // heavy tiles first
    const int h   = blockIdx.y;
    const int b   = blockIdx.z;
    const int tid = threadIdx.x;
    const int lane = tid & 31;
    const int wid  = tid >> 5;     // 0..3
    const int gid  = lane >> 2;
    const int tig  = lane & 3;
    const int q0   = qt * 64;
    const int wrow = wid * 16;
    const size_t rowbase = (size_t)b * SLEN;

    // ---- Stage Q tile (scaled by 1/8, hi/lo tf32 split): 64 rows ----
    #pragma unroll
    for (int it = 0; it < 8; it++) {
        const int idx = it * 128 + tid;       // 1024 float4
        const int r = idx >> 4, c4 = idx & 15;
        const float* qp = qkv + (rowbase + q0 + r) * 3072 + h * 64 + c4 * 4;
        const float4 v = *reinterpret_cast<const float4*>(qp);
        const float f[4] = {v.x * 0.125f, v.y * 0.125f, v.z * 0.125f, v.w * 0.125f};
        #pragma unroll
        for (int j = 0; j < 4; j++) {
            const uint32_t hi = f2tf32(f[j]);
            Qhi[r * STR + c4 * 4 + j] = hi;
            Qlo[r * STR + c4 * 4 + j] = f2tf32(f[j] - __uint_as_float(hi));
        }
    }
    __syncthreads();

    uint32_t qh[8][4], ql[8][4];
    #pragma unroll
    for (int kk = 0; kk < 8; kk++) {
        const int ba = (wrow + gid) * STR + kk * 8;
        const int bb = (wrow + gid + 8) * STR + kk * 8;
        qh[kk][0] = Qhi[ba + tig];     qh[kk][1] = Qhi[bb + tig];
        qh[kk][2] = Qhi[ba + tig + 4]; qh[kk][3] = Qhi[bb + tig + 4];
        ql[kk][0] = Qlo[ba + tig];     ql[kk][1] = Qlo[bb + tig];
        ql[kk][2] = Qlo[ba + tig + 4]; ql[kk][3] = Qlo[bb + tig + 4];
    }

    float oacc[8][4];
    #pragma unroll
    for (int nf = 0; nf < 8; nf++)
        #pragma unroll
        for (int e = 0; e < 4; e++) oacc[nf][e] = 0.f;
    float m0 = -INFINITY, m1 = -INFINITY, l0 = 0.f, l1 = 0.f;

    const int row0g = q0 + wrow + gid;
    const int row1g = row0g + 8;
    const int kend  = q0 + 64;

    // ---- K/V register prefetch (chunk 0): 8 float4 pairs ----
    float4 kpre[8], vpre[8];
    auto ldg_chunk = [&](int kb) {
        #pragma unroll
        for (int it = 0; it < 8; it++) {
            const int idx = it * 128 + tid;
            const int r = idx >> 4, c4 = idx & 15;
            const float* kp = qkv + (rowbase + kb + r) * 3072 + N_EMBED + h * 64 + c4 * 4;
            kpre[it] = *reinterpret_cast<const float4*>(kp);
            vpre[it] = *reinterpret_cast<const float4*>(kp + N_EMBED);
        }
    };
    ldg_chunk(0);

    for (int kb = 0; kb < kend; kb += 64) {
        __syncthreads();   // protect K/V/P writers vs prev readers (and Q staging, iter 0)

        // ---- STS prefetched chunk (tf32 cvt), then issue next LDG ----
        #pragma unroll
        for (int it = 0; it < 8; it++) {
            const int idx = it * 128 + tid;
            const int r = idx >> 4, c4 = idx & 15;
            uint32_t* kd = &Kh[r * STR + c4 * 4];
            uint32_t* vd = &Vs[r * STR + c4 * 4];
            kd[0] = f2tf32(kpre[it].x); kd[1] = f2tf32(kpre[it].y);
            kd[2] = f2tf32(kpre[it].z); kd[3] = f2tf32(kpre[it].w);
            vd[0] = f2tf32(vpre[it].x); vd[1] = f2tf32(vpre[it].y);
            vd[2] = f2tf32(vpre[it].z); vd[3] = f2tf32(vpre[it].w);
        }
        if (kb + 64 < kend) ldg_chunk(kb + 64);
        __syncthreads();

        // ---- S = Q K^T (2-term split: qh*k + ql*k) ----
        float sacc[8][4];
        #pragma unroll
        for (int nf = 0; nf < 8; nf++)
            #pragma unroll
            for (int e = 0; e < 4; e++) sacc[nf][e] = 0.f;

        #pragma unroll
        for (int kk = 0; kk < 8; kk++) {
            #pragma unroll
            for (int nf = 0; nf < 8; nf++) {
                const int kr = (nf * 8 + gid) * STR + kk * 8;
                uint32_t bh[2];
                bh[0] = Kh[kr + tig]; bh[1] = Kh[kr + tig + 4];
                mma_tf32(sacc[nf], qh[kk], bh);
                mma_tf32(sacc[nf], ql[kk], bh);
            }
        }

        // ---- causal mask (diagonal chunk only) ----
        if (kb + 63 > q0 + wrow) {
            #pragma unroll
            for (int nf = 0; nf < 8; nf++) {
                const int c = kb + nf * 8 + tig * 2;
                if (c     > row0g) sacc[nf][0] = -INFINITY;
                if (c + 1 > row0g) sacc[nf][1] = -INFINITY;
                if (c     > row1g) sacc[nf][2] = -INFINITY;
                if (c + 1 > row1g) sacc[nf][3] = -INFINITY;
            }
        }

        // ---- online softmax ----
        float mx0 = -INFINITY, mx1 = -INFINITY;
        #pragma unroll
        for (int nf = 0; nf < 8; nf++) {
            mx0 = fmaxf(mx0, fmaxf(sacc[nf][0], sacc[nf][1]));
            mx1 = fmaxf(mx1, fmaxf(sacc[nf][2], sacc[nf][3]));
        }
        mx0 = fmaxf(mx0, __shfl_xor_sync(0xffffffff, mx0, 1));
        mx0 = fmaxf(mx0, __shfl_xor_sync(0xffffffff, mx0, 2));
        mx1 = fmaxf(mx1, __shfl_xor_sync(0xffffffff, mx1, 1));
        mx1 = fmaxf(mx1, __shfl_xor_sync(0xffffffff, mx1, 2));

        const float mn0 = fmaxf(m0, mx0);
        const float mn1 = fmaxf(m1, mx1);
        const float a0 = __expf(m0 - mn0);
        const float a1 = __expf(m1 - mn1);
        m0 = mn0; m1 = mn1;

        float rs0 = 0.f, rs1 = 0.f;
        #pragma unroll
        for (int nf = 0; nf < 8; nf++) {
            const float p0 = __expf(sacc[nf][0] - m0);
            const float p1 = __expf(sacc[nf][1] - m0);
            const float p2 = __expf(sacc[nf][2] - m1);
            const float p3 = __expf(sacc[nf][3] - m1);
            rs0 += p0 + p1; rs1 += p2 + p3;
            uint2 u0; u0.x = f2tf32(p0); u0.y = f2tf32(p1);
            uint2 u1; u1.x = f2tf32(p2); u1.y = f2tf32(p3);
            *reinterpret_cast<uint2*>(&Ps[(wrow + gid)     * STR + nf * 8 + 2 * tig]) = u0;
            *reinterpret_cast<uint2*>(&Ps[(wrow + gid + 8) * STR + nf * 8 + 2 * tig]) = u1;
        }
        rs0 += __shfl_xor_sync(0xffffffff, rs0, 1);
        rs0 += __shfl_xor_sync(0xffffffff, rs0, 2);
        rs1 += __shfl_xor_sync(0xffffffff, rs1, 1);
        rs1 += __shfl_xor_sync(0xffffffff, rs1, 2);
        l0 = l0 * a0 + rs0;
        l1 = l1 * a1 + rs1;

        #pragma unroll
        for (int nf = 0; nf < 8; nf++) {
            oacc[nf][0] *= a0; oacc[nf][1] *= a0;
            oacc[nf][2] *= a1; oacc[nf][3] *= a1;
        }

        __syncwarp();   // Ps rows warp-private: order stores before loads

        // ---- O += P V ----
        #pragma unroll
        for (int kk = 0; kk < 8; kk++) {
            uint32_t a[4];
            const int pa = (wrow + gid) * STR + kk * 8;
            const int pb = (wrow + gid + 8) * STR + kk * 8;
            a[0] = Ps[pa + tig];     a[1] = Ps[pb + tig];
            a[2] = Ps[pa + tig + 4]; a[3] = Ps[pb + tig + 4];
            #pragma unroll
            for (int nf = 0; nf < 8; nf++) {
                uint32_t bv[2];
                bv[0] = Vs[(kk * 8 + tig)     * STR + nf * 8 + gid];
                bv[1] = Vs[(kk * 8 + tig + 4) * STR + nf * 8 + gid];
                mma_tf32(oacc[nf], a, bv);
            }
        }
    }

    // ---- epilogue: normalize, write y as tf32 BIT PATTERNS ----
    const float inv0 = 1.f / l0;
    const float inv1 = 1.f / l1;
    float* yp0 = y + (rowbase + row0g) * N_EMBED + h * 64;
    float* yp1 = y + (rowbase + row1g) * N_EMBED + h * 64;
    #pragma unroll
    for (int nf = 0; nf < 8; nf++) {
        float2 v0, v1;
        v0.x = __uint_as_float(f2tf32(oacc[nf][0] * inv0));
        v0.y = __uint_as_float(f2tf32(oacc[nf][1] * inv0));
        v1.x = __uint_as_float(f2tf32(oacc[nf][2] * inv1));
        v1.y = __uint_as_float(f2tf32(oacc[nf][3] * inv1));
        *reinterpret_cast<float2*>(yp0 + nf * 8 + 2 * tig) = v0;
        *reinterpret_cast<float2*>(yp1 + nf * 8 + 2 * tig) = v1;
    }
}

// ---------------------------------------------------------------------------
// kernel_launch
// ---------------------------------------------------------------------------
extern "C" void kernel_launch(void* const* d_in, const int* in_sizes, int n_in,
                              void* d_out, int out_size) {
    const float* x      = (const float*)d_in[0];
    const float* W_attn = (const float*)d_in[1];
    const float* b_attn = (const float*)d_in[2];
    const float* W_proj = (const float*)d_in[3];
    const float* b_proj = (const float*)d_in[4];
    float* out = (float*)d_out;

    float* qkv = nullptr; float* yb = nullptr; float* cv = nullptr;
    cudaGetSymbolAddress((void**)&qkv, g_qkv);
    cudaGetSymbolAddress((void**)&yb,  g_y);
    cudaGetSymbolAddress((void**)&cv,  g_cvt);

    float* x_t  = cv;                                          // [8192,1024]
    float* wa_t = x_t + (size_t)MROWS * N_EMBED;               // [1024,3072]
    float* wp_t = wa_t + (size_t)N_EMBED * 3 * N_EMBED;        // [1024,1024]

    cudaFuncSetAttribute(mma_gemm_kernel,
                         cudaFuncAttributeMaxDynamicSharedMemorySize, G_SMEM_BYTES);
    cudaFuncSetAttribute(flash_attn_mma_kernel,
                         cudaFuncAttributeMaxDynamicSharedMemorySize, FA_SMEM_BYTES);

    // 0) Pre-convert operands to tf32 bit patterns
    cvt_tf32_kernel<<<592, 256>>>(x,      x_t,  MROWS * N_EMBED);
    cvt_tf32_kernel<<<592, 256>>>(W_attn, wa_t, N_EMBED * 3 * N_EMBED);
    cvt_tf32_kernel<<<592, 256>>>(W_proj, wp_t, N_EMBED * N_EMBED);

    // 1) QKV GEMM: [8192,1024]tf32 @ [1024,3072]tf32 + b_attn -> fp32
    {
        dim3 grid(3 * N_EMBED / 128, MROWS / 128);
        mma_gemm_kernel<<<grid, 256, G_SMEM_BYTES>>>(x_t, wa_t, b_attn, qkv,
                                                     MROWS, 3 * N_EMBED, N_EMBED);
    }
    // 2) Causal flash attention (y written as tf32 bits)
    {
        dim3 grid(SLEN / 64, NHEADS, BATCH);
        flash_attn_mma_kernel<<<grid, 128, FA_SMEM_BYTES>>>(qkv, yb);
    }
    // 3) Output projection: y(tf32) @ Wproj(tf32) + b_proj -> out fp32
    {
        dim3 grid(N_EMBED / 128, MROWS / 128);
        mma_gemm_kernel<<<grid, 256, G_SMEM_BYTES>>>(yb, wp_t, b_proj, out,
                                                     MROWS, N_EMBED, N_EMBED);
    }
}

// round 10
// speedup vs baseline: 1.3483x; 1.3483x over previous
#include <cuda_runtime.h>
#include <cuda_fp16.h>
#include <math.h>
#include <stdint.h>

#define N_EMBED 1024
#define SLEN    2048
#define BATCH   4
#define NHEADS  16
#define HDIM    64
#define MROWS   (BATCH * SLEN)        // 8192

// Scratch (device globals: allocation-free rule)
__device__ float  g_qkv[(size_t)MROWS * 3 * N_EMBED];   // [8192, 3072] fp32
__device__ __half g_yh[(size_t)MROWS * N_EMBED];        // [8192, 1024] half
__device__ __half g_xh[(size_t)MROWS * N_EMBED];        // x half [8192,1024]
__device__ __half g_wa[(size_t)3 * N_EMBED * N_EMBED];  // Wattn^T half [3072,1024]
__device__ __half g_wp[(size_t)N_EMBED * N_EMBED];      // Wproj^T half [1024,1024]

// ---------------------------------------------------------------------------
// Helpers
// ---------------------------------------------------------------------------
__device__ __forceinline__ void mma_f16(float d[4], const uint32_t a[4], const uint32_t b[2]) {
    asm volatile(
        "mma.sync.aligned.m16n8k16.row.col.f32.f16.f16.f32 "
        "{%0,%1,%2,%3}, {%4,%5,%6,%7}, {%8,%9}, {%0,%1,%2,%3};"
        : "+f"(d[0]), "+f"(d[1]), "+f"(d[2]), "+f"(d[3])
        : "r"(a[0]), "r"(a[1]), "r"(a[2]), "r"(a[3]), "r"(b[0]), "r"(b[1]));
}
__device__ __forceinline__ uint32_t smem_u32(const void* p) {
    uint32_t a;
    asm("{ .reg .u64 t; cvta.to.shared.u64 t, %1; cvt.u32.u64 %0, t; }" : "=r"(a) : "l"(p));
    return a;
}
__device__ __forceinline__ void cp_async16(uint32_t saddr, const void* g) {
    asm volatile("cp.async.cg.shared.global [%0], [%1], 16;" :: "r"(saddr), "l"(g));
}
#define CP_COMMIT()  asm volatile("cp.async.commit_group;" ::: "memory")
#define CP_WAIT(n)   asm volatile("cp.async.wait_group %0;" :: "n"(n) : "memory")
__device__ __forceinline__ uint32_t pack_h2(float x, float y) {
    __half2 h = __floats2half2_rn(x, y);
    return *reinterpret_cast<uint32_t*>(&h);
}

// ---------------------------------------------------------------------------
// fp32 -> half elementwise (x), grid-stride, float4 in / 4 halfs out.
// ---------------------------------------------------------------------------
__global__ __launch_bounds__(256)
void cvt_half_kernel(const float* __restrict__ in, __half* __restrict__ out, int n) {
    const int stride = gridDim.x * blockDim.x * 4;
    for (int i = (blockIdx.x * blockDim.x + threadIdx.x) * 4; i < n; i += stride) {
        float4 v = *reinterpret_cast<const float4*>(in + i);
        uint2 o;
        o.x = pack_h2(v.x, v.y);
        o.y = pack_h2(v.z, v.w);
        *reinterpret_cast<uint2*>(out + i) = o;
    }
}

// ---------------------------------------------------------------------------
// Transpose + cvt: out[c][r] = (half) in[r][c].  in [R,C] fp32, out [C,R] half.
// ---------------------------------------------------------------------------
__global__ __launch_bounds__(256)
void transpose_half_kernel(const float* __restrict__ in, __half* __restrict__ out,
                           int R, int C) {
    __shared__ float t[32][33];
    const int c0 = blockIdx.x * 32, r0 = blockIdx.y * 32;
    const int tx = threadIdx.x, ty = threadIdx.y;   // 32 x 8
    #pragma unroll
    for (int i = ty; i < 32; i += 8)
        t[i][tx] = in[(size_t)(r0 + i) * C + c0 + tx];
    __syncthreads();
    #pragma unroll
    for (int i = ty; i < 32; i += 8)
        out[(size_t)(c0 + i) * R + r0 + tx] = __float2half_rn(t[tx][i]);
}

// ---------------------------------------------------------------------------
// fp16 mma.sync GEMM: C[M,N] = A[M,K] @ Bt[N,K]^T + bias[N]
// A half row-major [M,K]; Bt half row-major [N,K] (pre-transposed weights).
// BM=BN=128, BK=32; 256 threads = 8 warps (2x4), warp tile 64x32.
// 4-stage cp.async pipeline. smem rows 40 halfs (32 + pad) -> conflict-free.
// stage = (128+128)*40 halfs = 20480 B; 4 stages = 81920 B. 2 CTAs/SM.
// ---------------------------------------------------------------------------
#define G_RS 40                         // halfs per smem row
#define G_RSW 20                        // words per smem row
#define G_TSTG (128 * G_RS)             // halfs per A (or B) tile
#define G_STG_HALFS (2 * G_TSTG)        // halfs per stage
#define G_SMEM_BYTES (4 * G_STG_HALFS * 2)

__global__ __launch_bounds__(256, 2)
void mma_gemm_kernel(const __half* __restrict__ A, const __half* __restrict__ Bt,
                     const float* __restrict__ bias, float* __restrict__ C,
                     int M, int N, int K) {
    extern __shared__ uint32_t gsm[];   // word view of half smem

    const int tid   = threadIdx.x;
    const int lane  = tid & 31;
    const int wid   = tid >> 5;           // 0..7
    const int gid   = lane >> 2;
    const int tig   = lane & 3;
    const int warpM = wid >> 2;           // 0..1 -> 64 rows
    const int warpN = wid & 3;            // 0..3 -> 32 cols
    const int row0  = blockIdx.y * 128;
    const int col0  = blockIdx.x * 128;

    const uint32_t uS = smem_u32(gsm);

    // Per-stage loads: A 128 rows x 64B (4 chunks), B 128 rows x 64B.
    // 256 threads: thread t -> row t>>1, chunks (t&1)*2 + {0,1}.
    const int lrow = tid >> 1;
    const int lch  = (tid & 1) * 2;

    auto issue = [&](int kt, int stg) {
        const __half* Ag = A  + (size_t)(row0 + lrow) * K + kt * 32;
        const __half* Bg = Bt + (size_t)(col0 + lrow) * K + kt * 32;
        const uint32_t sa = uS + (uint32_t)(stg * G_STG_HALFS + lrow * G_RS) * 2;
        const uint32_t sb = sa + (uint32_t)G_TSTG * 2;
        #pragma unroll
        for (int i = 0; i < 2; i++) {
            const int c = lch + i;
            cp_async16(sa + c * 16, Ag + c * 8);
            cp_async16(sb + c * 16, Bg + c * 8);
        }
        CP_COMMIT();
    };

    float acc[4][4][4];
    #pragma unroll
    for (int i = 0; i < 4; i++)
        #pragma unroll
        for (int j = 0; j < 4; j++)
            #pragma unroll
            for (int r = 0; r < 4; r++) acc[i][j][r] = 0.f;

    const int NT = K / 32;

    issue(0, 0); issue(1, 1); issue(2, 2);

    for (int kt = 0; kt < NT; kt++) {
        if (kt < NT - 2) { CP_WAIT(2); } else { CP_WAIT(0); }
        __syncthreads();

        const uint32_t* As = gsm + (kt & 3) * (G_STG_HALFS / 2);
        const uint32_t* Bs = As + (G_TSTG / 2);

        #pragma unroll
        for (int ks = 0; ks < 2; ks++) {
            const int kw = ks * 8;      // word offset of k16 block
            uint32_t a[4][4], b[4][2];
            #pragma unroll
            for (int mf = 0; mf < 4; mf++) {
                const int r = warpM * 64 + mf * 16;
                a[mf][0] = As[(r + gid)     * G_RSW + kw + tig];
                a[mf][1] = As[(r + gid + 8) * G_RSW + kw + tig];
                a[mf][2] = As[(r + gid)     * G_RSW + kw + tig + 4];
                a[mf][3] = As[(r + gid + 8) * G_RSW + kw + tig + 4];
            }
            #pragma unroll
            for (int nf = 0; nf < 4; nf++) {
                const int c = warpN * 32 + nf * 8 + gid;
                b[nf][0] = Bs[c * G_RSW + kw + tig];
                b[nf][1] = Bs[c * G_RSW + kw + tig + 4];
            }
            #pragma unroll
            for (int mf = 0; mf < 4; mf++)
                #pragma unroll
                for (int nf = 0; nf < 4; nf++)
                    mma_f16(acc[mf][nf], a[mf], b[nf]);
        }
        if (kt + 3 < NT) issue(kt + 3, (kt + 3) & 3);
    }

    // Epilogue: add bias, store fp32
    #pragma unroll
    for (int mf = 0; mf < 4; mf++) {
        const size_t rbase = (size_t)row0 + warpM * 64 + mf * 16 + gid;
        #pragma unroll
        for (int nf = 0; nf < 4; nf++) {
            const int col = col0 + warpN * 32 + nf * 8 + tig * 2;
            const float2 bz = *reinterpret_cast<const float2*>(bias + col);
            float2 v0, v1;
            v0.x = acc[mf][nf][0] + bz.x; v0.y = acc[mf][nf][1] + bz.y;
            v1.x = acc[mf][nf][2] + bz.x; v1.y = acc[mf][nf][3] + bz.y;
            *reinterpret_cast<float2*>(C + rbase * N + col)       = v0;
            *reinterpret_cast<float2*>(C + (rbase + 8) * N + col) = v1;
        }
    }
}

// ---------------------------------------------------------------------------
// Flash attention, fp16 mma m16n8k16, 2-term QK (lo scaled by 512 in its own
// accumulator), K/V register prefetch, V stored transposed in smem.
// CTA = 64 q-rows x head x batch; 4 warps (128 thr); 64-key chunks; 2 CTAs/SM.
// SMEM halfs (row stride 72 = 36 words):
//   Kh[64 key][64 d] | Vt[64 d][64 key] | Ps[64 q][64 key]  = 192*72 halfs
//   Q overlay: Qhi over Kh, Qlo over Vt.
// Writes y as half (consumed by proj GEMM).
// ---------------------------------------------------------------------------
#define ASW 36                          // words per smem row (72 halfs)
#define FA_SMEM_BYTES (192 * ASW * 4)
#define QLO_SCALE 512.0f
#define QLO_INV   (1.0f / 512.0f)

__global__ __launch_bounds__(128, 2)
void flash_attn_mma_kernel(const float* __restrict__ qkv, __half* __restrict__ y) {
    extern __shared__ uint32_t sm[];
    uint32_t* Khw = sm;                       // 64*36 words
    uint32_t* Vtw = sm + 64 * ASW;            // 64*36
    uint32_t* Psw = sm + 128 * ASW;           // 64*36
    __half*   Vth = reinterpret_cast<__half*>(Vtw);
    uint32_t* Qhw = Khw;                      // overlay
    uint32_t* Qlw = Vtw;                      // overlay

    const int qt  = (gridDim.x - 1) - blockIdx.x;   // heavy tiles first
    const int h   = blockIdx.y;
    const int b   = blockIdx.z;
    const int tid = threadIdx.x;
    const int lane = tid & 31;
    const int wid  = tid >> 5;     // 0..3
    const int gid  = lane >> 2;
    const int tig  = lane & 3;
    const int q0   = qt * 64;
    const int wrow = wid * 16;
    const size_t rowbase = (size_t)b * SLEN;

    // ---- Stage Q (scaled 1/8): hi half + (residual*512) half ----
    #pragma unroll
    for (int it = 0; it < 8; it++) {
        const int idx = it * 128 + tid;       // 1024 float4
        const int r = idx >> 4, c4 = idx & 15;
        const float* qp = qkv + (rowbase + q0 + r) * 3072 + h * 64 + c4 * 4;
        const float4 v = *reinterpret_cast<const float4*>(qp);
        const float f[4] = {v.x * 0.125f, v.y * 0.125f, v.z * 0.125f, v.w * 0.125f};
        float hi[4], lo[4];
        #pragma unroll
        for (int j = 0; j < 4; j++) {
            const __half hh = __float2half_rn(f[j]);
            hi[j] = __half2float(hh);
            lo[j] = (f[j] - hi[j]) * QLO_SCALE;
        }
        const int w = r * ASW + c4 * 2;
        Qhw[w]     = pack_h2(hi[0], hi[1]);
        Qhw[w + 1] = pack_h2(hi[2], hi[3]);
        Qlw[w]     = pack_h2(lo[0], lo[1]);
        Qlw[w + 1] = pack_h2(lo[2], lo[3]);
    }
    __syncthreads();

    // Q fragments: 4 k16-steps over 64 dims
    uint32_t qh[4][4], ql[4][4];
    #pragma unroll
    for (int ks = 0; ks < 4; ks++) {
        const int ba = (wrow + gid) * ASW + ks * 8;
        const int bb = (wrow + gid + 8) * ASW + ks * 8;
        qh[ks][0] = Qhw[ba + tig];     qh[ks][1] = Qhw[bb + tig];
        qh[ks][2] = Qhw[ba + tig + 4]; qh[ks][3] = Qhw[bb + tig + 4];
        ql[ks][0] = Qlw[ba + tig];     ql[ks][1] = Qlw[bb + tig];
        ql[ks][2] = Qlw[ba + tig + 4]; ql[ks][3] = Qlw[bb + tig + 4];
    }

    float oacc[8][4];
    #pragma unroll
    for (int nf = 0; nf < 8; nf++)
        #pragma unroll
        for (int e = 0; e < 4; e++) oacc[nf][e] = 0.f;
    float m0 = -INFINITY, m1 = -INFINITY, l0 = 0.f, l1 = 0.f;

    const int row0g = q0 + wrow + gid;
    const int row1g = row0g + 8;
    const int kend  = q0 + 64;

    // ---- K/V register prefetch ----
    float4 kpre[8], vpre[8];
    auto ldg_chunk = [&](int kb) {
        #pragma unroll
        for (int it = 0; it < 8; it++) {
            const int idx = it * 128 + tid;
            const int r = idx >> 4, c4 = idx & 15;
            const float* kp = qkv + (rowbase + kb + r) * 3072 + N_EMBED + h * 64 + c4 * 4;
            kpre[it] = *reinterpret_cast<const float4*>(kp);
            vpre[it] = *reinterpret_cast<const float4*>(kp + N_EMBED);
        }
    };
    ldg_chunk(0);

    for (int kb = 0; kb < kend; kb += 64) {
        __syncthreads();   // protect K/V/P (and Q staging on first iter)

        // ---- STS: K row-major half, V transposed half ----
        #pragma unroll
        for (int it = 0; it < 8; it++) {
            const int idx = it * 128 + tid;
            const int r = idx >> 4, c4 = idx & 15;
            const int w = r * ASW + c4 * 2;
            Khw[w]     = pack_h2(kpre[it].x, kpre[it].y);
            Khw[w + 1] = pack_h2(kpre[it].z, kpre[it].w);
            const int d0 = c4 * 4;
            Vth[(d0 + 0) * 72 + r] = __float2half_rn(vpre[it].x);
            Vth[(d0 + 1) * 72 + r] = __float2half_rn(vpre[it].y);
            Vth[(d0 + 2) * 72 + r] = __float2half_rn(vpre[it].z);
            Vth[(d0 + 3) * 72 + r] = __float2half_rn(vpre[it].w);
        }
        if (kb + 64 < kend) ldg_chunk(kb + 64);
        __syncthreads();

        // ---- S = Q K^T (hi + lo/512 in separate accumulators) ----
        float sacc[8][4], slo[8][4];
        #pragma unroll
        for (int nf = 0; nf < 8; nf++)
            #pragma unroll
            for (int e = 0; e < 4; e++) { sacc[nf][e] = 0.f; slo[nf][e] = 0.f; }

        #pragma unroll
        for (int ks = 0; ks < 4; ks++) {
            #pragma unroll
            for (int nf = 0; nf < 8; nf++) {
                const int kr = (nf * 8 + gid) * ASW + ks * 8;
                uint32_t bh[2];
                bh[0] = Khw[kr + tig]; bh[1] = Khw[kr + tig + 4];
                mma_f16(sacc[nf], qh[ks], bh);
                mma_f16(slo[nf],  ql[ks], bh);
            }
        }
        #pragma unroll
        for (int nf = 0; nf < 8; nf++)
            #pragma unroll
            for (int e = 0; e < 4; e++) sacc[nf][e] += slo[nf][e] * QLO_INV;

        // ---- causal mask (diagonal chunk only) ----
        if (kb + 63 > q0 + wrow) {
            #pragma unroll
            for (int nf = 0; nf < 8; nf++) {
                const int c = kb + nf * 8 + tig * 2;
                if (c     > row0g) sacc[nf][0] = -INFINITY;
                if (c + 1 > row0g) sacc[nf][1] = -INFINITY;
                if (c     > row1g) sacc[nf][2] = -INFINITY;
                if (c + 1 > row1g) sacc[nf][3] = -INFINITY;
            }
        }

        // ---- online softmax ----
        float mx0 = -INFINITY, mx1 = -INFINITY;
        #pragma unroll
        for (int nf = 0; nf < 8; nf++) {
            mx0 = fmaxf(mx0, fmaxf(sacc[nf][0], sacc[nf][1]));
            mx1 = fmaxf(mx1, fmaxf(sacc[nf][2], sacc[nf][3]));
        }
        mx0 = fmaxf(mx0, __shfl_xor_sync(0xffffffff, mx0, 1));
        mx0 = fmaxf(mx0, __shfl_xor_sync(0xffffffff, mx0, 2));
        mx1 = fmaxf(mx1, __shfl_xor_sync(0xffffffff, mx1, 1));
        mx1 = fmaxf(mx1, __shfl_xor_sync(0xffffffff, mx1, 2));

        const float mn0 = fmaxf(m0, mx0);
        const float mn1 = fmaxf(m1, mx1);
        const float a0 = __expf(m0 - mn0);
        const float a1 = __expf(m1 - mn1);
        m0 = mn0; m1 = mn1;

        float rs0 = 0.f, rs1 = 0.f;
        #pragma unroll
        for (int nf = 0; nf < 8; nf++) {
            const float p0 = __expf(sacc[nf][0] - m0);
            const float p1 = __expf(sacc[nf][1] - m0);
            const float p2 = __expf(sacc[nf][2] - m1);
            const float p3 = __expf(sacc[nf][3] - m1);
            rs0 += p0 + p1; rs1 += p2 + p3;
            Psw[(wrow + gid)     * ASW + nf * 4 + tig] = pack_h2(p0, p1);
            Psw[(wrow + gid + 8) * ASW + nf * 4 + tig] = pack_h2(p2, p3);
        }
        rs0 += __shfl_xor_sync(0xffffffff, rs0, 1);
        rs0 += __shfl_xor_sync(0xffffffff, rs0, 2);
        rs1 += __shfl_xor_sync(0xffffffff, rs1, 1);
        rs1 += __shfl_xor_sync(0xffffffff, rs1, 2);
        l0 = l0 * a0 + rs0;
        l1 = l1 * a1 + rs1;

        #pragma unroll
        for (int nf = 0; nf < 8; nf++) {
            oacc[nf][0] *= a0; oacc[nf][1] *= a0;
            oacc[nf][2] *= a1; oacc[nf][3] *= a1;
        }

        __syncwarp();   // Ps rows warp-private: order stores before loads

        // ---- O += P V  (4 k16-steps over 64 keys) ----
        #pragma unroll
        for (int ks = 0; ks < 4; ks++) {
            uint32_t a[4];
            const int pa = (wrow + gid) * ASW + ks * 8;
            const int pb = (wrow + gid + 8) * ASW + ks * 8;
            a[0] = Psw[pa + tig];     a[1] = Psw[pb + tig];
            a[2] = Psw[pa + tig + 4]; a[3] = Psw[pb + tig + 4];
            #pragma unroll
            for (int nf = 0; nf < 8; nf++) {
                const int vr = (nf * 8 + gid) * ASW + ks * 8;
                uint32_t bv[2];
                bv[0] = Vtw[vr + tig]; bv[1] = Vtw[vr + tig + 4];
                mma_f16(oacc[nf], a, bv);
            }
        }
    }

    // ---- epilogue: normalize, write y as half ----
    const float inv0 = 1.f / l0;
    const float inv1 = 1.f / l1;
    __half* yp0 = y + (rowbase + row0g) * N_EMBED + h * 64;
    __half* yp1 = y + (rowbase + row1g) * N_EMBED + h * 64;
    #pragma unroll
    for (int nf = 0; nf < 8; nf++) {
        *reinterpret_cast<uint32_t*>(yp0 + nf * 8 + 2 * tig) =
            pack_h2(oacc[nf][0] * inv0, oacc[nf][1] * inv0);
        *reinterpret_cast<uint32_t*>(yp1 + nf * 8 + 2 * tig) =
            pack_h2(oacc[nf][2] * inv1, oacc[nf][3] * inv1);
    }
}

// ---------------------------------------------------------------------------
// kernel_launch
// ---------------------------------------------------------------------------
extern "C" void kernel_launch(void* const* d_in, const int* in_sizes, int n_in,
                              void* d_out, int out_size) {
    const float* x      = (const float*)d_in[0];
    const float* W_attn = (const float*)d_in[1];
    const float* b_attn = (const float*)d_in[2];
    const float* W_proj = (const float*)d_in[3];
    const float* b_proj = (const float*)d_in[4];
    float* out = (float*)d_out;

    float* qkv = nullptr; __half* yh = nullptr;
    __half* xh = nullptr; __half* wa = nullptr; __half* wp = nullptr;
    cudaGetSymbolAddress((void**)&qkv, g_qkv);
    cudaGetSymbolAddress((void**)&yh,  g_yh);
    cudaGetSymbolAddress((void**)&xh,  g_xh);
    cudaGetSymbolAddress((void**)&wa,  g_wa);
    cudaGetSymbolAddress((void**)&wp,  g_wp);

    cudaFuncSetAttribute(mma_gemm_kernel,
                         cudaFuncAttributeMaxDynamicSharedMemorySize, G_SMEM_BYTES);
    cudaFuncSetAttribute(flash_attn_mma_kernel,
                         cudaFuncAttributeMaxDynamicSharedMemorySize, FA_SMEM_BYTES);

    // 0) Pre-convert: x -> half; weights -> half transposed [N][K]
    cvt_half_kernel<<<592, 256>>>(x, xh, MROWS * N_EMBED);
    {
        dim3 blk(32, 8);
        transpose_half_kernel<<<dim3(3 * N_EMBED / 32, N_EMBED / 32), blk>>>(
            W_attn, wa, N_EMBED, 3 * N_EMBED);
        transpose_half_kernel<<<dim3(N_EMBED / 32, N_EMBED / 32), blk>>>(
            W_proj, wp, N_EMBED, N_EMBED);
    }

    // 1) QKV GEMM (fp16 m16n8k16): [8192,1024] @ [1024,3072] + b_attn -> fp32
    {
        dim3 grid(3 * N_EMBED / 128, MROWS / 128);
        mma_gemm_kernel<<<grid, 256, G_SMEM_BYTES>>>(xh, wa, b_attn, qkv,
                                                     MROWS, 3 * N_EMBED, N_EMBED);
    }
    // 2) Causal flash attention (fp16 MMAs, y written as half)
    {
        dim3 grid(SLEN / 64, NHEADS, BATCH);
        flash_attn_mma_kernel<<<grid, 128, FA_SMEM_BYTES>>>(qkv, yh);
    }
    // 3) Output projection (fp16): y(half) @ Wproj^T(half) + b_proj -> fp32
    {
        dim3 grid(N_EMBED / 128, MROWS / 128);
        mma_gemm_kernel<<<grid, 256, G_SMEM_BYTES>>>(yh, wp, b_proj, out,
                                                     MROWS, N_EMBED, N_EMBED);
    }
}

// round 11
// speedup vs baseline: 1.5515x; 1.1507x over previous
#include <cuda_runtime.h>
#include <cuda_fp16.h>
#include <math.h>
#include <stdint.h>

#define N_EMBED 1024
#define SLEN    2048
#define BATCH   4
#define NHEADS  16
#define HDIM    64
#define MROWS   (BATCH * SLEN)        // 8192

// Scratch (device globals: allocation-free rule)
__device__ __half g_qhi[(size_t)MROWS * N_EMBED];       // Q hi (scaled 1/8)
__device__ __half g_qlo[(size_t)MROWS * N_EMBED];       // Q residual *512
__device__ __half g_kh[(size_t)MROWS * N_EMBED];        // K half
__device__ __half g_vh[(size_t)MROWS * N_EMBED];        // V half
__device__ __half g_yh[(size_t)MROWS * N_EMBED];        // attention out half
__device__ __half g_xh[(size_t)MROWS * N_EMBED];        // x half
__device__ __half g_wa[(size_t)3 * N_EMBED * N_EMBED];  // Wattn^T half [3072,1024]
__device__ __half g_wp[(size_t)N_EMBED * N_EMBED];      // Wproj^T half [1024,1024]

// ---------------------------------------------------------------------------
// Helpers
// ---------------------------------------------------------------------------
__device__ __forceinline__ void mma_f16(float d[4], const uint32_t a[4], const uint32_t b[2]) {
    asm volatile(
        "mma.sync.aligned.m16n8k16.row.col.f32.f16.f16.f32 "
        "{%0,%1,%2,%3}, {%4,%5,%6,%7}, {%8,%9}, {%0,%1,%2,%3};"
        : "+f"(d[0]), "+f"(d[1]), "+f"(d[2]), "+f"(d[3])
        : "r"(a[0]), "r"(a[1]), "r"(a[2]), "r"(a[3]), "r"(b[0]), "r"(b[1]));
}
__device__ __forceinline__ uint32_t smem_u32(const void* p) {
    uint32_t a;
    asm("{ .reg .u64 t; cvta.to.shared.u64 t, %1; cvt.u32.u64 %0, t; }" : "=r"(a) : "l"(p));
    return a;
}
__device__ __forceinline__ void cp_async16(uint32_t saddr, const void* g) {
    asm volatile("cp.async.cg.shared.global [%0], [%1], 16;" :: "r"(saddr), "l"(g));
}
#define CP_COMMIT()  asm volatile("cp.async.commit_group;" ::: "memory")
#define CP_WAIT(n)   asm volatile("cp.async.wait_group %0;" :: "n"(n) : "memory")
__device__ __forceinline__ uint32_t pack_h2(float x, float y) {
    __half2 h = __floats2half2_rn(x, y);
    return *reinterpret_cast<uint32_t*>(&h);
}

// ---------------------------------------------------------------------------
// fp32 -> half elementwise (x), grid-stride.
// ---------------------------------------------------------------------------
__global__ __launch_bounds__(256)
void cvt_half_kernel(const float* __restrict__ in, __half* __restrict__ out, int n) {
    const int stride = gridDim.x * blockDim.x * 4;
    for (int i = (blockIdx.x * blockDim.x + threadIdx.x) * 4; i < n; i += stride) {
        float4 v = *reinterpret_cast<const float4*>(in + i);
        uint2 o;
        o.x = pack_h2(v.x, v.y);
        o.y = pack_h2(v.z, v.w);
        *reinterpret_cast<uint2*>(out + i) = o;
    }
}

// ---------------------------------------------------------------------------
// Transpose + cvt: out[c][r] = (half) in[r][c].
// ---------------------------------------------------------------------------
__global__ __launch_bounds__(256)
void transpose_half_kernel(const float* __restrict__ in, __half* __restrict__ out,
                           int R, int C) {
    __shared__ float t[32][33];
    const int c0 = blockIdx.x * 32, r0 = blockIdx.y * 32;
    const int tx = threadIdx.x, ty = threadIdx.y;   // 32 x 8
    #pragma unroll
    for (int i = ty; i < 32; i += 8)
        t[i][tx] = in[(size_t)(r0 + i) * C + c0 + tx];
    __syncthreads();
    #pragma unroll
    for (int i = ty; i < 32; i += 8)
        out[(size_t)(c0 + i) * R + r0 + tx] = __float2half_rn(t[tx][i]);
}

// ---------------------------------------------------------------------------
// fp16 mma.sync GEMM: C = A[M,K] @ Bt[N,K]^T + bias.
// mode 0: C fp32.  mode 1 (QKV): col-range-dependent half outputs:
//   cols [0,1024): Q -> qhi/qlo (scaled 1/8, residual*512)
//   cols [1024,2048): K -> kh half;  [2048,3072): V -> vh half.
// BM=BN=128, BK=32; 256 thr = 8 warps (2x4), warp tile 64x32; 4-stage cp.async.
// ---------------------------------------------------------------------------
#define G_RS 40
#define G_RSW 20
#define G_TSTG (128 * G_RS)
#define G_STG_HALFS (2 * G_TSTG)
#define G_SMEM_BYTES (4 * G_STG_HALFS * 2)

__global__ __launch_bounds__(256, 2)
void mma_gemm_kernel(const __half* __restrict__ A, const __half* __restrict__ Bt,
                     const float* __restrict__ bias, float* __restrict__ C,
                     __half* qhi, __half* qlo, __half* kh, __half* vh,
                     int M, int N, int K, int mode) {
    extern __shared__ uint32_t gsm[];

    const int tid   = threadIdx.x;
    const int lane  = tid & 31;
    const int wid   = tid >> 5;
    const int gid   = lane >> 2;
    const int tig   = lane & 3;
    const int warpM = wid >> 2;
    const int warpN = wid & 3;
    const int row0  = blockIdx.y * 128;
    const int col0  = blockIdx.x * 128;

    const uint32_t uS = smem_u32(gsm);
    const int lrow = tid >> 1;
    const int lch  = (tid & 1) * 2;

    auto issue = [&](int kt, int stg) {
        const __half* Ag = A  + (size_t)(row0 + lrow) * K + kt * 32;
        const __half* Bg = Bt + (size_t)(col0 + lrow) * K + kt * 32;
        const uint32_t sa = uS + (uint32_t)(stg * G_STG_HALFS + lrow * G_RS) * 2;
        const uint32_t sb = sa + (uint32_t)G_TSTG * 2;
        #pragma unroll
        for (int i = 0; i < 2; i++) {
            const int c = lch + i;
            cp_async16(sa + c * 16, Ag + c * 8);
            cp_async16(sb + c * 16, Bg + c * 8);
        }
        CP_COMMIT();
    };

    float acc[4][4][4];
    #pragma unroll
    for (int i = 0; i < 4; i++)
        #pragma unroll
        for (int j = 0; j < 4; j++)
            #pragma unroll
            for (int r = 0; r < 4; r++) acc[i][j][r] = 0.f;

    const int NT = K / 32;

    issue(0, 0); issue(1, 1); issue(2, 2);

    for (int kt = 0; kt < NT; kt++) {
        if (kt < NT - 2) { CP_WAIT(2); } else { CP_WAIT(0); }
        __syncthreads();

        const uint32_t* As = gsm + (kt & 3) * (G_STG_HALFS / 2);
        const uint32_t* Bs = As + (G_TSTG / 2);

        #pragma unroll
        for (int ks = 0; ks < 2; ks++) {
            const int kw = ks * 8;
            uint32_t a[4][4], b[4][2];
            #pragma unroll
            for (int mf = 0; mf < 4; mf++) {
                const int r = warpM * 64 + mf * 16;
                a[mf][0] = As[(r + gid)     * G_RSW + kw + tig];
                a[mf][1] = As[(r + gid + 8) * G_RSW + kw + tig];
                a[mf][2] = As[(r + gid)     * G_RSW + kw + tig + 4];
                a[mf][3] = As[(r + gid + 8) * G_RSW + kw + tig + 4];
            }
            #pragma unroll
            for (int nf = 0; nf < 4; nf++) {
                const int c = warpN * 32 + nf * 8 + gid;
                b[nf][0] = Bs[c * G_RSW + kw + tig];
                b[nf][1] = Bs[c * G_RSW + kw + tig + 4];
            }
            #pragma unroll
            for (int mf = 0; mf < 4; mf++)
                #pragma unroll
                for (int nf = 0; nf < 4; nf++)
                    mma_f16(acc[mf][nf], a[mf], b[nf]);
        }
        if (kt + 3 < NT) issue(kt + 3, (kt + 3) & 3);
    }

    auto emit_q = [&](size_t r, int c, float a0, float a1) {
        const float qa = a0 * 0.125f, qb = a1 * 0.125f;
        const __half ha = __float2half_rn(qa), hb = __float2half_rn(qb);
        __half2 hh; hh.x = ha; hh.y = hb;
        *reinterpret_cast<uint32_t*>(&qhi[r * N_EMBED + c]) =
            *reinterpret_cast<uint32_t*>(&hh);
        const float la = (qa - __half2float(ha)) * 512.f;
        const float lb = (qb - __half2float(hb)) * 512.f;
        *reinterpret_cast<uint32_t*>(&qlo[r * N_EMBED + c]) = pack_h2(la, lb);
    };

    #pragma unroll
    for (int mf = 0; mf < 4; mf++) {
        const size_t rb0 = (size_t)row0 + warpM * 64 + mf * 16 + gid;
        const size_t rb1 = rb0 + 8;
        #pragma unroll
        for (int nf = 0; nf < 4; nf++) {
            const int col = col0 + warpN * 32 + nf * 8 + tig * 2;
            const float2 bz = *reinterpret_cast<const float2*>(bias + col);
            const float o00 = acc[mf][nf][0] + bz.x, o01 = acc[mf][nf][1] + bz.y;
            const float o10 = acc[mf][nf][2] + bz.x, o11 = acc[mf][nf][3] + bz.y;
            if (mode == 0) {
                float2 v0, v1;
                v0.x = o00; v0.y = o01; v1.x = o10; v1.y = o11;
                *reinterpret_cast<float2*>(C + rb0 * N + col) = v0;
                *reinterpret_cast<float2*>(C + rb1 * N + col) = v1;
            } else if (col0 < 1024) {
                emit_q(rb0, col, o00, o01);
                emit_q(rb1, col, o10, o11);
            } else if (col0 < 2048) {
                const int c = col - 1024;
                *reinterpret_cast<uint32_t*>(&kh[rb0 * N_EMBED + c]) = pack_h2(o00, o01);
                *reinterpret_cast<uint32_t*>(&kh[rb1 * N_EMBED + c]) = pack_h2(o10, o11);
            } else {
                const int c = col - 2048;
                *reinterpret_cast<uint32_t*>(&vh[rb0 * N_EMBED + c]) = pack_h2(o00, o01);
                *reinterpret_cast<uint32_t*>(&vh[rb1 * N_EMBED + c]) = pack_h2(o10, o11);
            }
        }
    }
}

// ---------------------------------------------------------------------------
// Flash attention, fp16 MMAs, cp.async staging (no cvt), ldmatrix.trans for V.
// CTA = 64 q-rows x head x batch; 4 warps (128 thr); 64-key chunks; 2 CTAs/SM.
// SMEM halfs (rows of 72 = 36 words):
//   K0[64][72] @0 | V0 @4608 | K1 @9216 | V1 @13824 | Ps[64][72] @18432
//   Q overlay: Qhi @0, Qlo @4608 (read to regs before any K/V issue).
// Total 23040 halfs = 46080 B.
// ---------------------------------------------------------------------------
#define AH 72
#define AHW 36
#define FA_SMEM_BYTES 46080
#define QLO_INV (1.0f / 512.0f)

__global__ __launch_bounds__(128, 2)
void flash_attn_mma_kernel(const __half* __restrict__ qhi, const __half* __restrict__ qlo,
                           const __half* __restrict__ kh, const __half* __restrict__ vh,
                           __half* __restrict__ y) {
    extern __shared__ __half sh[];
    uint32_t* shw = reinterpret_cast<uint32_t*>(sh);
    const uint32_t uS = smem_u32(sh);

    const int qt  = (gridDim.x - 1) - blockIdx.x;   // heavy tiles first
    const int h   = blockIdx.y;
    const int b   = blockIdx.z;
    const int tid = threadIdx.x;
    const int lane = tid & 31;
    const int wid  = tid >> 5;     // 0..3
    const int gid  = lane >> 2;
    const int tig  = lane & 3;
    const int q0   = qt * 64;
    const int wrow = wid * 16;
    const size_t rowbase = (size_t)b * SLEN;
    const int hofs = h * 64;

    const int srow = tid >> 1;          // staging row 0..63
    const int sch  = (tid & 1) * 4;     // 4 chunks of 16B each

    // ---- Q staging (cp.async into overlay) ----
    {
        const __half* gq = qhi + (rowbase + q0 + srow) * N_EMBED + hofs;
        const __half* gl = qlo + (rowbase + q0 + srow) * N_EMBED + hofs;
        const uint32_t dq = uS + (uint32_t)(srow * AH) * 2;
        const uint32_t dl = uS + (uint32_t)(4608 + srow * AH) * 2;
        #pragma unroll
        for (int i = 0; i < 4; i++) {
            cp_async16(dq + (sch + i) * 16, gq + (sch + i) * 8);
            cp_async16(dl + (sch + i) * 16, gl + (sch + i) * 8);
        }
        CP_COMMIT();
        CP_WAIT(0);
    }
    __syncthreads();

    // ---- Q fragments (4 k16-steps over 64 dims) ----
    uint32_t qh[4][4], ql[4][4];
    #pragma unroll
    for (int ks = 0; ks < 4; ks++) {
        const int ba = (wrow + gid) * AHW + ks * 8;
        const int bb = (wrow + gid + 8) * AHW + ks * 8;
        qh[ks][0] = shw[ba + tig];          qh[ks][1] = shw[bb + tig];
        qh[ks][2] = shw[ba + tig + 4];      qh[ks][3] = shw[bb + tig + 4];
        ql[ks][0] = shw[2304 + ba + tig];   ql[ks][1] = shw[2304 + bb + tig];
        ql[ks][2] = shw[2304 + ba + tig + 4];
        ql[ks][3] = shw[2304 + bb + tig + 4];
    }
    __syncthreads();   // all warps done with overlay before K/V cp.async lands

    auto issue_kv = [&](int kb, int buf) {
        const __half* gk = kh + (rowbase + kb + srow) * N_EMBED + hofs;
        const __half* gv = vh + (rowbase + kb + srow) * N_EMBED + hofs;
        const uint32_t dk = uS + (uint32_t)(buf * 9216 + srow * AH) * 2;
        const uint32_t dv = dk + 4608 * 2;
        #pragma unroll
        for (int i = 0; i < 4; i++) {
            cp_async16(dk + (sch + i) * 16, gk + (sch + i) * 8);
            cp_async16(dv + (sch + i) * 16, gv + (sch + i) * 8);
        }
        CP_COMMIT();
    };

    issue_kv(0, 0);

    float oacc[8][4];
    #pragma unroll
    for (int nf = 0; nf < 8; nf++)
        #pragma unroll
        for (int e = 0; e < 4; e++) oacc[nf][e] = 0.f;
    float m0 = -INFINITY, m1 = -INFINITY, l0 = 0.f, l1 = 0.f;

    const int row0g = q0 + wrow + gid;
    const int row1g = row0g + 8;
    const int nch   = qt + 1;

    uint32_t* Psw = shw + 9216;   // word base of Ps

    // ldmatrix lane-fixed addressing for V
    const int lm  = lane >> 3;                 // matrix id 0..3
    const int lrw = lane & 7;
    const int km  = ((lm & 1) << 3) + lrw;     // key offset within k16
    const int cm  = (lm >> 1) * 8;             // col offset within n16

    for (int i = 0; i < nch; i++) {
        const int buf = i & 1;
        const int kb  = i * 64;
        if (i + 1 < nch) { issue_kv(kb + 64, buf ^ 1); CP_WAIT(1); }
        else             { CP_WAIT(0); }
        __syncthreads();

        const uint32_t* Kw = shw + buf * 4608;

        // ---- S = Q K^T (hi + lo/512, separate accumulators) ----
        float sacc[8][4], slo[8][4];
        #pragma unroll
        for (int nf = 0; nf < 8; nf++)
            #pragma unroll
            for (int e = 0; e < 4; e++) { sacc[nf][e] = 0.f; slo[nf][e] = 0.f; }

        #pragma unroll
        for (int ks = 0; ks < 4; ks++) {
            #pragma unroll
            for (int nf = 0; nf < 8; nf++) {
                const int kr = (nf * 8 + gid) * AHW + ks * 8;
                uint32_t bh[2];
                bh[0] = Kw[kr + tig]; bh[1] = Kw[kr + tig + 4];
                mma_f16(sacc[nf], qh[ks], bh);
                mma_f16(slo[nf],  ql[ks], bh);
            }
        }
        #pragma unroll
        for (int nf = 0; nf < 8; nf++)
            #pragma unroll
            for (int e = 0; e < 4; e++) sacc[nf][e] += slo[nf][e] * QLO_INV;

        // ---- causal mask (diagonal chunk only) ----
        if (kb + 63 > q0 + wrow) {
            #pragma unroll
            for (int nf = 0; nf < 8; nf++) {
                const int c = kb + nf * 8 + tig * 2;
                if (c     > row0g) sacc[nf][0] = -INFINITY;
                if (c + 1 > row0g) sacc[nf][1] = -INFINITY;
                if (c     > row1g) sacc[nf][2] = -INFINITY;
                if (c + 1 > row1g) sacc[nf][3] = -INFINITY;
            }
        }

        // ---- online softmax ----
        float mx0 = -INFINITY, mx1 = -INFINITY;
        #pragma unroll
        for (int nf = 0; nf < 8; nf++) {
            mx0 = fmaxf(mx0, fmaxf(sacc[nf][0], sacc[nf][1]));
            mx1 = fmaxf(mx1, fmaxf(sacc[nf][2], sacc[nf][3]));
        }
        mx0 = fmaxf(mx0, __shfl_xor_sync(0xffffffff, mx0, 1));
        mx0 = fmaxf(mx0, __shfl_xor_sync(0xffffffff, mx0, 2));
        mx1 = fmaxf(mx1, __shfl_xor_sync(0xffffffff, mx1, 1));
        mx1 = fmaxf(mx1, __shfl_xor_sync(0xffffffff, mx1, 2));

        const float mn0 = fmaxf(m0, mx0);
        const float mn1 = fmaxf(m1, mx1);
        const float a0 = __expf(m0 - mn0);
        const float a1 = __expf(m1 - mn1);
        m0 = mn0; m1 = mn1;

        float rs0 = 0.f, rs1 = 0.f;
        #pragma unroll
        for (int nf = 0; nf < 8; nf++) {
            const float p0 = __expf(sacc[nf][0] - m0);
            const float p1 = __expf(sacc[nf][1] - m0);
            const float p2 = __expf(sacc[nf][2] - m1);
            const float p3 = __expf(sacc[nf][3] - m1);
            rs0 += p0 + p1; rs1 += p2 + p3;
            Psw[(wrow + gid)     * AHW + nf * 4 + tig] = pack_h2(p0, p1);
            Psw[(wrow + gid + 8) * AHW + nf * 4 + tig] = pack_h2(p2, p3);
        }
        rs0 += __shfl_xor_sync(0xffffffff, rs0, 1);
        rs0 += __shfl_xor_sync(0xffffffff, rs0, 2);
        rs1 += __shfl_xor_sync(0xffffffff, rs1, 1);
        rs1 += __shfl_xor_sync(0xffffffff, rs1, 2);
        l0 = l0 * a0 + rs0;
        l1 = l1 * a1 + rs1;

        #pragma unroll
        for (int nf = 0; nf < 8; nf++) {
            oacc[nf][0] *= a0; oacc[nf][1] *= a0;
            oacc[nf][2] *= a1; oacc[nf][3] *= a1;
        }

        __syncwarp();   // Ps rows warp-private: order stores before loads

        // ---- O += P V  (V fragments via ldmatrix.x4.trans) ----
        const uint32_t vbase = uS + (uint32_t)(4608 + buf * 9216 + km * AH + cm) * 2;
        #pragma unroll
        for (int ks = 0; ks < 4; ks++) {
            uint32_t a[4];
            const int pa = (wrow + gid) * AHW + ks * 8;
            const int pb = (wrow + gid + 8) * AHW + ks * 8;
            a[0] = Psw[pa + tig];     a[1] = Psw[pb + tig];
            a[2] = Psw[pa + tig + 4]; a[3] = Psw[pb + tig + 4];
            #pragma unroll
            for (int nfp = 0; nfp < 4; nfp++) {
                uint32_t r0, r1, r2, r3;
                const uint32_t addr = vbase + ks * (16 * AH * 2) + nfp * 32;
                asm volatile(
                    "ldmatrix.sync.aligned.m8n8.x4.trans.shared.b16 {%0,%1,%2,%3}, [%4];"
                    : "=r"(r0), "=r"(r1), "=r"(r2), "=r"(r3) : "r"(addr));
                uint32_t b0[2] = {r0, r1};
                uint32_t b1[2] = {r2, r3};
                mma_f16(oacc[nfp * 2],     a, b0);
                mma_f16(oacc[nfp * 2 + 1], a, b1);
            }
        }
        __syncthreads();   // all reads of buf done before it is refilled
    }

    // ---- epilogue: normalize, write y as half ----
    const float inv0 = 1.f / l0;
    const float inv1 = 1.f / l1;
    __half* yp0 = y + (rowbase + row0g) * N_EMBED + hofs;
    __half* yp1 = y + (rowbase + row1g) * N_EMBED + hofs;
    #pragma unroll
    for (int nf = 0; nf < 8; nf++) {
        *reinterpret_cast<uint32_t*>(yp0 + nf * 8 + 2 * tig) =
            pack_h2(oacc[nf][0] * inv0, oacc[nf][1] * inv0);
        *reinterpret_cast<uint32_t*>(yp1 + nf * 8 + 2 * tig) =
            pack_h2(oacc[nf][2] * inv1, oacc[nf][3] * inv1);
    }
}

// ---------------------------------------------------------------------------
// kernel_launch
// ---------------------------------------------------------------------------
extern "C" void kernel_launch(void* const* d_in, const int* in_sizes, int n_in,
                              void* d_out, int out_size) {
    const float* x      = (const float*)d_in[0];
    const float* W_attn = (const float*)d_in[1];
    const float* b_attn = (const float*)d_in[2];
    const float* W_proj = (const float*)d_in[3];
    const float* b_proj = (const float*)d_in[4];
    float* out = (float*)d_out;

    __half *qhi = nullptr, *qlo = nullptr, *khp = nullptr, *vhp = nullptr;
    __half *yh = nullptr, *xh = nullptr, *wa = nullptr, *wp = nullptr;
    cudaGetSymbolAddress((void**)&qhi, g_qhi);
    cudaGetSymbolAddress((void**)&qlo, g_qlo);
    cudaGetSymbolAddress((void**)&khp, g_kh);
    cudaGetSymbolAddress((void**)&vhp, g_vh);
    cudaGetSymbolAddress((void**)&yh,  g_yh);
    cudaGetSymbolAddress((void**)&xh,  g_xh);
    cudaGetSymbolAddress((void**)&wa,  g_wa);
    cudaGetSymbolAddress((void**)&wp,  g_wp);

    cudaFuncSetAttribute(mma_gemm_kernel,
                         cudaFuncAttributeMaxDynamicSharedMemorySize, G_SMEM_BYTES);
    cudaFuncSetAttribute(flash_attn_mma_kernel,
                         cudaFuncAttributeMaxDynamicSharedMemorySize, FA_SMEM_BYTES);

    // 0) Pre-convert: x -> half; weights -> half transposed [N][K]
    cvt_half_kernel<<<592, 256>>>(x, xh, MROWS * N_EMBED);
    {
        dim3 blk(32, 8);
        transpose_half_kernel<<<dim3(3 * N_EMBED / 32, N_EMBED / 32), blk>>>(
            W_attn, wa, N_EMBED, 3 * N_EMBED);
        transpose_half_kernel<<<dim3(N_EMBED / 32, N_EMBED / 32), blk>>>(
            W_proj, wp, N_EMBED, N_EMBED);
    }

    // 1) QKV GEMM -> split half outputs (Q hi/lo scaled, K, V)
    {
        dim3 grid(3 * N_EMBED / 128, MROWS / 128);
        mma_gemm_kernel<<<grid, 256, G_SMEM_BYTES>>>(
            xh, wa, b_attn, nullptr, qhi, qlo, khp, vhp,
            MROWS, 3 * N_EMBED, N_EMBED, 1);
    }
    // 2) Causal flash attention (all-half staging)
    {
        dim3 grid(SLEN / 64, NHEADS, BATCH);
        flash_attn_mma_kernel<<<grid, 128, FA_SMEM_BYTES>>>(qhi, qlo, khp, vhp, yh);
    }
    // 3) Output projection: y(half) @ Wproj^T(half) + b_proj -> fp32
    {
        dim3 grid(N_EMBED / 128, MROWS / 128);
        mma_gemm_kernel<<<grid, 256, G_SMEM_BYTES>>>(
            yh, wp, b_proj, out, nullptr, nullptr, nullptr, nullptr,
            MROWS, N_EMBED, N_EMBED, 0);
    }
}